// round 6
// baseline (speedup 1.0000x reference)
#include <cuda_runtime.h>
#include <cuda_fp16.h>
#include <cstdint>
#include <math.h>

#define BATCH 4
#define SEQ   2048
#define DM    1024
#define NH    16
#define DH    64
#define MROWS (BATCH*SEQ)   // 8192

// ---------------------------------------------------------------------------
// Scratch (__device__ globals; no runtime allocation). 256B aligned for cp.async.
// ---------------------------------------------------------------------------
__device__ __align__(256) __half g_qh[(size_t)BATCH*NH*SEQ*DH];   // [B,H,S,dh]
__device__ __align__(256) __half g_kh[(size_t)BATCH*NH*SEQ*DH];
__device__ __align__(256) __half g_vh[(size_t)BATCH*NH*SEQ*DH];
__device__ __align__(256) __half g_ao[(size_t)MROWS*DM];          // [B*S, D]
__device__ __align__(256) __half g_qc[(size_t)MROWS*DM];          // half input copies
__device__ __align__(256) __half g_kc[(size_t)MROWS*DM];
__device__ __align__(256) __half g_vc[(size_t)MROWS*DM];
__device__ __align__(256) __half g_wt[4][(size_t)DM*DM];          // W^T as half

// ---------------------------------------------------------------------------
// Helpers
// ---------------------------------------------------------------------------
__device__ __forceinline__ uint32_t smem_u32(const void* p) {
    uint32_t a;
    asm("{ .reg .u64 t; cvta.to.shared.u64 t, %1; cvt.u32.u64 %0, t; }" : "=r"(a) : "l"(p));
    return a;
}
__device__ __forceinline__ void cp16(uint32_t dst, const void* src) {
    asm volatile("cp.async.cg.shared.global [%0], [%1], 16;\n" :: "r"(dst), "l"(src) : "memory");
}
__device__ __forceinline__ void cp_commit() { asm volatile("cp.async.commit_group;" ::: "memory"); }

__device__ __forceinline__ uint32_t pack_h2(float a, float b) {
    __half2 h = __floats2half2_rn(a, b);
    return *(uint32_t*)&h;
}

// D(f32 16x8) += A(f16 16x16, row) * B(f16 16x8, col)
__device__ __forceinline__ void mma16(float* d, const uint32_t* a, uint32_t b0, uint32_t b1) {
    asm volatile(
        "mma.sync.aligned.m16n8k16.row.col.f32.f16.f16.f32 "
        "{%0,%1,%2,%3}, {%4,%5,%6,%7}, {%8,%9}, {%0,%1,%2,%3};"
        : "+f"(d[0]), "+f"(d[1]), "+f"(d[2]), "+f"(d[3])
        : "r"(a[0]), "r"(a[1]), "r"(a[2]), "r"(a[3]), "r"(b0), "r"(b1));
}

// ---------------------------------------------------------------------------
// fp16 HMMA GEMM: C[8192,1024] = A_h @ Wt_h^T + bias
// A row-major [M,K] half; Wt row-major [N,K] half.
// Block 128x128, BK=32 halfs, 256 threads (8 warps, warp tile 32x64).
// ---------------------------------------------------------------------------
#define GPADH 40                      // halfs per smem row (pad 8)
#define GTILEH (128*GPADH)            // 5120 halfs per tile
#define GBUFH  (2*GTILEH)             // A+B per buffer
#define TCG_SMEM (2*GBUFH*2)          // 40960 bytes

template<bool HEAD_OUT, typename OutT>
__global__ __launch_bounds__(256) void tc_gemm(
    const __half* __restrict__ A, const __half* __restrict__ Wt,
    const float* __restrict__ bias, OutT* __restrict__ C)
{
    extern __shared__ __half smh[];
    const uint32_t sbase = smem_u32(smh);
    const int tid = threadIdx.x;
    const int lane = tid & 31, wid = tid >> 5;
    const int g = lane >> 2, t = lane & 3;
    const int wm = wid & 3, wn = wid >> 2;       // warp tile: rows wm*32, cols wn*64

    const int m0 = blockIdx.y * 128;
    const int n0 = blockIdx.x * 128;

    auto issue = [&](int kc, int buf) {
        const int kcol = kc * 32;
        const uint32_t base = sbase + (uint32_t)buf * GBUFH * 2;
        #pragma unroll
        for (int i = tid; i < 512; i += 256) {
            const int r = i >> 2, c8 = (i & 3) * 8;
            cp16(base + (uint32_t)(r * GPADH + c8) * 2, A + (size_t)(m0 + r) * DM + kcol + c8);
        }
        const uint32_t bb = base + GTILEH * 2;
        #pragma unroll
        for (int i = tid; i < 512; i += 256) {
            const int r = i >> 2, c8 = (i & 3) * 8;
            cp16(bb + (uint32_t)(r * GPADH + c8) * 2, Wt + (size_t)(n0 + r) * DM + kcol + c8);
        }
        cp_commit();
    };

    float acc[2][8][4];
    #pragma unroll
    for (int mf = 0; mf < 2; mf++)
        #pragma unroll
        for (int nf = 0; nf < 8; nf++)
            #pragma unroll
            for (int c = 0; c < 4; c++) acc[mf][nf][c] = 0.f;

    issue(0, 0);
    issue(1, 1);

    #pragma unroll 1
    for (int c = 0; c < 32; c++) {
        const int buf = c & 1;
        if (c + 1 < 32) asm volatile("cp.async.wait_group 1;" ::: "memory");
        else            asm volatile("cp.async.wait_group 0;" ::: "memory");
        __syncthreads();

        const __half* as = smh + buf * GBUFH;
        const __half* bs = as + GTILEH;
        #pragma unroll
        for (int kk = 0; kk < 2; kk++) {
            const int k = kk * 16 + 2 * t;
            uint32_t a[2][4];
            #pragma unroll
            for (int mf = 0; mf < 2; mf++) {
                const int r = wm * 32 + mf * 16 + g;
                a[mf][0] = *(const uint32_t*)(as + r * GPADH + k);
                a[mf][1] = *(const uint32_t*)(as + (r + 8) * GPADH + k);
                a[mf][2] = *(const uint32_t*)(as + r * GPADH + k + 8);
                a[mf][3] = *(const uint32_t*)(as + (r + 8) * GPADH + k + 8);
            }
            #pragma unroll
            for (int nf = 0; nf < 8; nf++) {
                const int n = wn * 64 + nf * 8 + g;
                const uint32_t b0 = *(const uint32_t*)(bs + n * GPADH + k);
                const uint32_t b1 = *(const uint32_t*)(bs + n * GPADH + k + 8);
                mma16(acc[0][nf], a[0], b0, b1);
                mma16(acc[1][nf], a[1], b0, b1);
            }
        }
        __syncthreads();
        if (c + 2 < 32) issue(c + 2, buf);
    }

    // Epilogue: direct stores (+bias)
    #pragma unroll
    for (int mf = 0; mf < 2; mf++) {
        #pragma unroll
        for (int nf = 0; nf < 8; nf++) {
            const int rl = m0 + wm * 32 + mf * 16 + g;
            const int cl = n0 + wn * 64 + nf * 8 + 2 * t;
            #pragma unroll
            for (int cc = 0; cc < 4; cc++) {
                const int row = rl + (cc >> 1) * 8;
                const int col = cl + (cc & 1);
                const float val = acc[mf][nf][cc] + bias[col];
                if (HEAD_OUT) {
                    const int b = row >> 11, s = row & (SEQ - 1);
                    const int h = col >> 6,  d = col & (DH - 1);
                    C[((size_t)(b * NH + h) * SEQ + s) * DH + d] = (OutT)val;
                } else {
                    C[(size_t)row * DM + col] = (OutT)val;
                }
            }
        }
    }
}

// ---------------------------------------------------------------------------
// Conversion kernels
// ---------------------------------------------------------------------------
__global__ __launch_bounds__(256) void cvt_f16_kernel(const float4* __restrict__ in,
                                                      uint2* __restrict__ out)
{
    const size_t i = (size_t)blockIdx.x * blockDim.x + threadIdx.x;
    const float4 v = in[i];
    uint2 u;
    u.x = pack_h2(v.x, v.y);
    u.y = pack_h2(v.z, v.w);
    out[i] = u;
}

// Transpose 1024x1024 + convert: Wt[n][k] = half(W[k][n])
__global__ __launch_bounds__(256) void transpose_cvt_kernel(const float* __restrict__ W,
                                                            __half* __restrict__ Wt)
{
    __shared__ float tbuf[32][33];
    const int tx = threadIdx.x, ty = threadIdx.y;     // 32 x 8
    const int bx = blockIdx.x * 32, by = blockIdx.y * 32;
    #pragma unroll
    for (int j = 0; j < 32; j += 8)
        tbuf[ty + j][tx] = W[(size_t)(by + ty + j) * DM + bx + tx];
    __syncthreads();
    #pragma unroll
    for (int j = 0; j < 32; j += 8)
        Wt[(size_t)(bx + ty + j) * DM + by + tx] = __float2half_rn(tbuf[tx][ty + j]);
}

// ---------------------------------------------------------------------------
// Flash attention on fp16 HMMA. 128 threads (4 warps); warp w owns q rows
// [w*16, w*16+16). BQ=64 q-rows per block, 64-row K/V tiles.
// smem (halfs): Qs[64][72], Ks[64][72], Vt[64][72] (d-major!), Ps[64][72]
// ---------------------------------------------------------------------------
#define FP 72
#define FQ_OFF 0
#define FK_OFF (64*FP)
#define FV_OFF (2*64*FP)
#define FP_OFF (3*64*FP)
#define FLASH_SMEM (4*64*FP*2)     // 36864 bytes

__global__ __launch_bounds__(128) void flash_kernel(__half* __restrict__ out)
{
    extern __shared__ __half sm[];
    __half* Qs = sm + FQ_OFF;
    __half* Ks = sm + FK_OFF;
    __half* Vt = sm + FV_OFF;      // [d][s]
    __half* Ps = sm + FP_OFF;
    const uint32_t sbase = smem_u32(sm);

    const int tid = threadIdx.x;
    const int lane = tid & 31, w = tid >> 5;
    const int g = lane >> 2, t = lane & 3;
    const int bh = blockIdx.y;
    const int q0 = blockIdx.x * 64;

    const __half* Qg = g_qh + (size_t)bh * SEQ * DH;
    const __half* Kg = g_kh + (size_t)bh * SEQ * DH;
    const __half* Vg = g_vh + (size_t)bh * SEQ * DH;

    // Q tile via cp.async (64 rows x 64 halfs; 8 x 16B per row)
    #pragma unroll
    for (int i = tid; i < 512; i += 128) {
        const int r = i >> 3, c8 = (i & 7) * 8;
        cp16(sbase + (uint32_t)(FQ_OFF + r * FP + c8) * 2, Qg + (size_t)(q0 + r) * DH + c8);
    }
    cp_commit();

    float oacc[8][4];
    #pragma unroll
    for (int nf = 0; nf < 8; nf++)
        #pragma unroll
        for (int c = 0; c < 4; c++) oacc[nf][c] = 0.f;
    float m0r = -3.0e38f, m1r = -3.0e38f, l0 = 0.f, l1 = 0.f;

    const float sc = 0.125f;         // 1/sqrt(64)
    const int qrow_l = w * 16 + g;   // A-frag rows qrow_l, qrow_l+8

    #pragma unroll 1
    for (int k0 = 0; k0 < SEQ; k0 += 64) {
        __syncthreads();   // prior tile fully consumed
        // K tile via cp.async
        #pragma unroll
        for (int i = tid; i < 512; i += 128) {
            const int r = i >> 3, c8 = (i & 7) * 8;
            cp16(sbase + (uint32_t)(FK_OFF + r * FP + c8) * 2, Kg + (size_t)(k0 + r) * DH + c8);
        }
        cp_commit();
        // V tile transposed into Vt[d][s]
        #pragma unroll
        for (int i = tid; i < 1024; i += 128) {
            const int r = i >> 4, c4 = (i & 15) * 4;          // s=r, d=c4..c4+3
            const __half2 v01 = *(const __half2*)(Vg + (size_t)(k0 + r) * DH + c4);
            const __half2 v23 = *(const __half2*)(Vg + (size_t)(k0 + r) * DH + c4 + 2);
            Vt[(c4 + 0) * FP + r] = __low2half(v01);
            Vt[(c4 + 1) * FP + r] = __high2half(v01);
            Vt[(c4 + 2) * FP + r] = __low2half(v23);
            Vt[(c4 + 3) * FP + r] = __high2half(v23);
        }
        asm volatile("cp.async.wait_group 0;" ::: "memory");
        __syncthreads();

        // S = Q K^T : warp computes 16x64
        float sacc[8][4];
        #pragma unroll
        for (int nf = 0; nf < 8; nf++)
            #pragma unroll
            for (int c = 0; c < 4; c++) sacc[nf][c] = 0.f;

        #pragma unroll
        for (int kk = 0; kk < 4; kk++) {
            const int k = kk * 16 + 2 * t;
            uint32_t a[4];
            a[0] = *(const uint32_t*)(Qs + qrow_l * FP + k);
            a[1] = *(const uint32_t*)(Qs + (qrow_l + 8) * FP + k);
            a[2] = *(const uint32_t*)(Qs + qrow_l * FP + k + 8);
            a[3] = *(const uint32_t*)(Qs + (qrow_l + 8) * FP + k + 8);
            #pragma unroll
            for (int nf = 0; nf < 8; nf++) {
                const int n = nf * 8 + g;
                mma16(sacc[nf], a,
                      *(const uint32_t*)(Ks + n * FP + k),
                      *(const uint32_t*)(Ks + n * FP + k + 8));
            }
        }

        // Online softmax on fragments (rows qrow_l, qrow_l+8)
        float mx0 = -3.0e38f, mx1 = -3.0e38f;
        #pragma unroll
        for (int nf = 0; nf < 8; nf++) {
            sacc[nf][0] *= sc; sacc[nf][1] *= sc;
            sacc[nf][2] *= sc; sacc[nf][3] *= sc;
            mx0 = fmaxf(mx0, fmaxf(sacc[nf][0], sacc[nf][1]));
            mx1 = fmaxf(mx1, fmaxf(sacc[nf][2], sacc[nf][3]));
        }
        mx0 = fmaxf(mx0, __shfl_xor_sync(0xffffffffu, mx0, 1));
        mx0 = fmaxf(mx0, __shfl_xor_sync(0xffffffffu, mx0, 2));
        mx1 = fmaxf(mx1, __shfl_xor_sync(0xffffffffu, mx1, 1));
        mx1 = fmaxf(mx1, __shfl_xor_sync(0xffffffffu, mx1, 2));

        const float mn0 = fmaxf(m0r, mx0), mn1 = fmaxf(m1r, mx1);
        const float al0 = __expf(m0r - mn0), al1 = __expf(m1r - mn1);
        float s0 = 0.f, s1 = 0.f;
        #pragma unroll
        for (int nf = 0; nf < 8; nf++) {
            float p;
            p = __expf(sacc[nf][0] - mn0); sacc[nf][0] = p; s0 += p;
            p = __expf(sacc[nf][1] - mn0); sacc[nf][1] = p; s0 += p;
            p = __expf(sacc[nf][2] - mn1); sacc[nf][2] = p; s1 += p;
            p = __expf(sacc[nf][3] - mn1); sacc[nf][3] = p; s1 += p;
        }
        s0 += __shfl_xor_sync(0xffffffffu, s0, 1);
        s0 += __shfl_xor_sync(0xffffffffu, s0, 2);
        s1 += __shfl_xor_sync(0xffffffffu, s1, 1);
        s1 += __shfl_xor_sync(0xffffffffu, s1, 2);
        l0 = l0 * al0 + s0; m0r = mn0;
        l1 = l1 * al1 + s1; m1r = mn1;

        // Rescale O; stage P as half2 in warp-private rows
        #pragma unroll
        for (int nf = 0; nf < 8; nf++) {
            oacc[nf][0] *= al0; oacc[nf][1] *= al0;
            oacc[nf][2] *= al1; oacc[nf][3] *= al1;
            const int pc = nf * 8 + 2 * t;
            *(uint32_t*)(Ps + qrow_l * FP + pc)       = pack_h2(sacc[nf][0], sacc[nf][1]);
            *(uint32_t*)(Ps + (qrow_l + 8) * FP + pc) = pack_h2(sacc[nf][2], sacc[nf][3]);
        }
        __syncwarp();

        // O += P V : A = Ps rows (16x64), B = Vt[d][s]
        #pragma unroll
        for (int kk = 0; kk < 4; kk++) {
            const int k = kk * 16 + 2 * t;
            uint32_t a[4];
            a[0] = *(const uint32_t*)(Ps + qrow_l * FP + k);
            a[1] = *(const uint32_t*)(Ps + (qrow_l + 8) * FP + k);
            a[2] = *(const uint32_t*)(Ps + qrow_l * FP + k + 8);
            a[3] = *(const uint32_t*)(Ps + (qrow_l + 8) * FP + k + 8);
            #pragma unroll
            for (int nf = 0; nf < 8; nf++) {
                const int n = nf * 8 + g;
                mma16(oacc[nf], a,
                      *(const uint32_t*)(Vt + n * FP + k),
                      *(const uint32_t*)(Vt + n * FP + k + 8));
            }
        }
    }

    // Normalize + write half to [B,S,D]
    const int b = bh >> 4, h = bh & 15;
    const float inv0 = 1.f / l0, inv1 = 1.f / l1;
    const int qrow = q0 + qrow_l;
    #pragma unroll
    for (int nf = 0; nf < 8; nf++) {
        const int col = h * DH + nf * 8 + 2 * t;
        *(uint32_t*)(out + (size_t)(b * SEQ + qrow) * DM + col) =
            pack_h2(oacc[nf][0] * inv0, oacc[nf][1] * inv0);
        *(uint32_t*)(out + (size_t)(b * SEQ + qrow + 8) * DM + col) =
            pack_h2(oacc[nf][2] * inv1, oacc[nf][3] * inv1);
    }
}

// ---------------------------------------------------------------------------
extern "C" void kernel_launch(void* const* d_in, const int* in_sizes, int n_in,
                              void* d_out, int out_size)
{
    const float* v  = (const float*)d_in[0];
    const float* k  = (const float*)d_in[1];
    const float* q  = (const float*)d_in[2];
    const float* wq = (const float*)d_in[3];
    const float* bq = (const float*)d_in[4];
    const float* wk = (const float*)d_in[5];
    const float* bk = (const float*)d_in[6];
    const float* wv = (const float*)d_in[7];
    const float* bv = (const float*)d_in[8];
    const float* wo = (const float*)d_in[9];
    const float* bo = (const float*)d_in[10];
    float* out = (float*)d_out;

    __half *qh, *kh, *vh, *ao, *qc, *kc, *vc, *wt;
    cudaGetSymbolAddress((void**)&qh, g_qh);
    cudaGetSymbolAddress((void**)&kh, g_kh);
    cudaGetSymbolAddress((void**)&vh, g_vh);
    cudaGetSymbolAddress((void**)&ao, g_ao);
    cudaGetSymbolAddress((void**)&qc, g_qc);
    cudaGetSymbolAddress((void**)&kc, g_kc);
    cudaGetSymbolAddress((void**)&vc, g_vc);
    cudaGetSymbolAddress((void**)&wt, g_wt);

    // 1) Convert inputs to half; transpose+convert weights
    const int cvt_blocks = (MROWS * DM / 4) / 256;   // 8192
    cvt_f16_kernel<<<cvt_blocks, 256>>>((const float4*)q, (uint2*)qc);
    cvt_f16_kernel<<<cvt_blocks, 256>>>((const float4*)k, (uint2*)kc);
    cvt_f16_kernel<<<cvt_blocks, 256>>>((const float4*)v, (uint2*)vc);

    dim3 tgrid(DM / 32, DM / 32);
    dim3 tblk(32, 8);
    transpose_cvt_kernel<<<tgrid, tblk>>>(wq, wt + 0 * (size_t)DM * DM);
    transpose_cvt_kernel<<<tgrid, tblk>>>(wk, wt + 1 * (size_t)DM * DM);
    transpose_cvt_kernel<<<tgrid, tblk>>>(wv, wt + 2 * (size_t)DM * DM);
    transpose_cvt_kernel<<<tgrid, tblk>>>(wo, wt + 3 * (size_t)DM * DM);

    // 2) Projections (fp16 HMMA, half outputs in head layout)
    dim3 gproj(DM / 128, MROWS / 128);   // (8, 64)
    tc_gemm<true,  __half><<<gproj, 256, TCG_SMEM>>>(qc, wt + 0 * (size_t)DM * DM, bq, qh);
    tc_gemm<true,  __half><<<gproj, 256, TCG_SMEM>>>(kc, wt + 1 * (size_t)DM * DM, bk, kh);
    tc_gemm<true,  __half><<<gproj, 256, TCG_SMEM>>>(vc, wt + 2 * (size_t)DM * DM, bv, vh);

    // 3) Attention (fp16 HMMA flash)
    dim3 gattn(SEQ / 64, BATCH * NH);    // (32, 64)
    flash_kernel<<<gattn, 128, FLASH_SMEM>>>(ao);

    // 4) Output projection (fp16 HMMA, f32 output)
    tc_gemm<false, float><<<gproj, 256, TCG_SMEM>>>(ao, wt + 3 * (size_t)DM * DM, bo, out);
}

// round 7
// speedup vs baseline: 2.2327x; 2.2327x over previous
#include <cuda_runtime.h>
#include <cuda_fp16.h>
#include <cstdint>
#include <math.h>

#define BATCH 4
#define SEQ   2048
#define DM    1024
#define NH    16
#define DH    64
#define MROWS (BATCH*SEQ)   // 8192

// ---------------------------------------------------------------------------
// Scratch (__device__ globals; no runtime allocation). 256B aligned.
// ---------------------------------------------------------------------------
__device__ __align__(256) __half g_qh[(size_t)BATCH*NH*SEQ*DH];   // [b,h,s,d]
__device__ __align__(256) __half g_kh[(size_t)BATCH*NH*SEQ*DH];   // [b,h,s,d]
__device__ __align__(256) __half g_vt[(size_t)BATCH*NH*DH*SEQ];   // [b,h,d,s]  TRANSPOSED
__device__ __align__(256) __half g_ao[(size_t)MROWS*DM];          // [b*s, d_model]
__device__ __align__(256) __half g_qc[(size_t)MROWS*DM];
__device__ __align__(256) __half g_kc[(size_t)MROWS*DM];
__device__ __align__(256) __half g_vc[(size_t)MROWS*DM];
__device__ __align__(256) __half g_wt[4][(size_t)DM*DM];          // W^T as half

// ---------------------------------------------------------------------------
// Helpers
// ---------------------------------------------------------------------------
__device__ __forceinline__ uint32_t smem_u32(const void* p) {
    uint32_t a;
    asm("{ .reg .u64 t; cvta.to.shared.u64 t, %1; cvt.u32.u64 %0, t; }" : "=r"(a) : "l"(p));
    return a;
}
__device__ __forceinline__ void cp16(uint32_t dst, const void* src) {
    asm volatile("cp.async.cg.shared.global [%0], [%1], 16;\n" :: "r"(dst), "l"(src) : "memory");
}
__device__ __forceinline__ void cp_commit() { asm volatile("cp.async.commit_group;" ::: "memory"); }

__device__ __forceinline__ uint32_t pack_h2(float a, float b) {
    __half2 h = __floats2half2_rn(a, b);
    return *(uint32_t*)&h;
}

// D(f32 16x8) += A(f16 16x16, row) * B(f16 16x8, col)
__device__ __forceinline__ void mma16(float* d, const uint32_t* a, uint32_t b0, uint32_t b1) {
    asm volatile(
        "mma.sync.aligned.m16n8k16.row.col.f32.f16.f16.f32 "
        "{%0,%1,%2,%3}, {%4,%5,%6,%7}, {%8,%9}, {%0,%1,%2,%3};"
        : "+f"(d[0]), "+f"(d[1]), "+f"(d[2]), "+f"(d[3])
        : "r"(a[0]), "r"(a[1]), "r"(a[2]), "r"(a[3]), "r"(b0), "r"(b1));
}
__device__ __forceinline__ void ldsm4(uint32_t& r0, uint32_t& r1, uint32_t& r2, uint32_t& r3,
                                      uint32_t addr) {
    asm volatile("ldmatrix.sync.aligned.m8n8.x4.shared.b16 {%0,%1,%2,%3}, [%4];"
                 : "=r"(r0), "=r"(r1), "=r"(r2), "=r"(r3) : "r"(addr));
}

// ---------------------------------------------------------------------------
// fp16 HMMA GEMM: C[8192,1024] = A_h @ Wt_h^T + bias
// MODE 0: float plain [M,DM]; MODE 1: half head [b,h,s,d]; MODE 2: half [b,h,d,s]
// Block 128x128, BK=32 halfs, 256 threads (8 warps, warp tile 32x64).
// ---------------------------------------------------------------------------
#define GPADH 40
#define GTILEH (128*GPADH)
#define GBUFH  (2*GTILEH)
#define TCG_SMEM (2*GBUFH*2)          // 40960 bytes

template<int MODE, typename OutT>
__global__ __launch_bounds__(256) void tc_gemm(
    const __half* __restrict__ A, const __half* __restrict__ Wt,
    const float* __restrict__ bias, OutT* __restrict__ C)
{
    extern __shared__ __half smh[];
    const uint32_t sbase = smem_u32(smh);
    const int tid = threadIdx.x;
    const int lane = tid & 31, wid = tid >> 5;
    const int g = lane >> 2, t = lane & 3;
    const int wm = wid & 3, wn = wid >> 2;

    // ldmatrix lane address components
    const int lr = lane & 15;                 // A: row within 16
    const int lc = (lane >> 4) << 3;          // A: col half (0/8)
    const int br = (lane & 7) + ((lane >> 4) << 3);   // B: n within 16
    const int bc = ((lane >> 3) & 1) << 3;            // B: k half (0/8)

    const int m0 = blockIdx.y * 128;
    const int n0 = blockIdx.x * 128;

    auto issue = [&](int kc, int buf) {
        const int kcol = kc * 32;
        const uint32_t base = sbase + (uint32_t)buf * GBUFH * 2;
        #pragma unroll
        for (int i = tid; i < 512; i += 256) {
            const int r = i >> 2, c8 = (i & 3) * 8;
            cp16(base + (uint32_t)(r * GPADH + c8) * 2, A + (size_t)(m0 + r) * DM + kcol + c8);
        }
        const uint32_t bb = base + GTILEH * 2;
        #pragma unroll
        for (int i = tid; i < 512; i += 256) {
            const int r = i >> 2, c8 = (i & 3) * 8;
            cp16(bb + (uint32_t)(r * GPADH + c8) * 2, Wt + (size_t)(n0 + r) * DM + kcol + c8);
        }
        cp_commit();
    };

    float acc[2][8][4];
    #pragma unroll
    for (int mf = 0; mf < 2; mf++)
        #pragma unroll
        for (int nf = 0; nf < 8; nf++)
            #pragma unroll
            for (int c = 0; c < 4; c++) acc[mf][nf][c] = 0.f;

    issue(0, 0);
    issue(1, 1);

    #pragma unroll 1
    for (int c = 0; c < 32; c++) {
        const int buf = c & 1;
        if (c + 1 < 32) asm volatile("cp.async.wait_group 1;" ::: "memory");
        else            asm volatile("cp.async.wait_group 0;" ::: "memory");
        __syncthreads();

        const uint32_t asb = sbase + (uint32_t)buf * GBUFH * 2;
        const uint32_t bsb = asb + GTILEH * 2;
        #pragma unroll
        for (int kk = 0; kk < 2; kk++) {
            uint32_t a[2][4];
            #pragma unroll
            for (int mf = 0; mf < 2; mf++)
                ldsm4(a[mf][0], a[mf][1], a[mf][2], a[mf][3],
                      asb + (uint32_t)((wm * 32 + mf * 16 + lr) * GPADH + kk * 16 + lc) * 2);
            #pragma unroll
            for (int np = 0; np < 4; np++) {
                uint32_t b0, b1, b2, b3;
                ldsm4(b0, b1, b2, b3,
                      bsb + (uint32_t)((wn * 64 + np * 16 + br) * GPADH + kk * 16 + bc) * 2);
                mma16(acc[0][2 * np],     a[0], b0, b1);
                mma16(acc[1][2 * np],     a[1], b0, b1);
                mma16(acc[0][2 * np + 1], a[0], b2, b3);
                mma16(acc[1][2 * np + 1], a[1], b2, b3);
            }
        }
        __syncthreads();
        if (c + 2 < 32) issue(c + 2, buf);
    }

    if (MODE != 2) {
        #pragma unroll
        for (int mf = 0; mf < 2; mf++) {
            #pragma unroll
            for (int nf = 0; nf < 8; nf++) {
                const int rl = m0 + wm * 32 + mf * 16 + g;
                const int cl = n0 + wn * 64 + nf * 8 + 2 * t;
                #pragma unroll
                for (int cc = 0; cc < 4; cc++) {
                    const int row = rl + (cc >> 1) * 8;
                    const int col = cl + (cc & 1);
                    const float val = acc[mf][nf][cc] + bias[col];
                    if (MODE == 1) {
                        const int b = row >> 11, s = row & (SEQ - 1);
                        const int h = col >> 6,  d = col & (DH - 1);
                        C[((size_t)(b * NH + h) * SEQ + s) * DH + d] = (OutT)val;
                    } else {
                        C[(size_t)row * DM + col] = (OutT)val;
                    }
                }
            }
        }
    } else {
        // Transposed head output [b,h,d,s] via smem staging (for V)
        __syncthreads();
        __half* st = smh;                    // [32][136]
        const int b = m0 >> 11;
        const int s_base = m0 & (SEQ - 1);
        #pragma unroll 1
        for (int ch = 0; ch < 4; ch++) {
            if (wn == (ch >> 1)) {
                const int nfb = (ch & 1) * 4;
                #pragma unroll
                for (int mf = 0; mf < 2; mf++)
                    #pragma unroll
                    for (int nfo = 0; nfo < 4; nfo++) {
                        const int nf = nfb + nfo;
                        #pragma unroll
                        for (int cc = 0; cc < 4; cc++) {
                            const int row = wm * 32 + mf * 16 + g + (cc >> 1) * 8;
                            const int col_l = wn * 64 + nf * 8 + 2 * t + (cc & 1);
                            st[(col_l - ch * 32) * 136 + row] =
                                __float2half_rn(acc[mf][nf][cc] + bias[n0 + col_l]);
                        }
                    }
            }
            __syncthreads();
            {
                const int cidx = tid >> 3;        // 0..31
                const int part = tid & 7;         // 16 rows each
                const int col = n0 + ch * 32 + cidx;
                const int h = col >> 6, d = col & (DH - 1);
                __half* dstp = (__half*)C + ((size_t)(b * NH + h) * DH + d) * SEQ + s_base + part * 16;
                const __half* srcp = st + cidx * 136 + part * 16;
                *(uint4*)(dstp)     = *(const uint4*)(srcp);
                *(uint4*)(dstp + 8) = *(const uint4*)(srcp + 8);
            }
            __syncthreads();
        }
    }
}

// ---------------------------------------------------------------------------
// Fused conversion kernels
// ---------------------------------------------------------------------------
__global__ __launch_bounds__(256) void cvt3_kernel(
    const float4* __restrict__ q, const float4* __restrict__ k, const float4* __restrict__ v,
    uint2* __restrict__ qc, uint2* __restrict__ kc, uint2* __restrict__ vc)
{
    const float4* src = (blockIdx.y == 0) ? q : (blockIdx.y == 1) ? k : v;
    uint2* dst        = (blockIdx.y == 0) ? qc : (blockIdx.y == 1) ? kc : vc;
    const size_t i = (size_t)blockIdx.x * blockDim.x + threadIdx.x;
    const float4 x = src[i];
    uint2 u;
    u.x = pack_h2(x.x, x.y);
    u.y = pack_h2(x.z, x.w);
    dst[i] = u;
}

__global__ __launch_bounds__(256) void transpose4_kernel(
    const float* __restrict__ wq, const float* __restrict__ wk,
    const float* __restrict__ wv, const float* __restrict__ wo,
    __half* __restrict__ wt)
{
    const float* W = (blockIdx.z == 0) ? wq : (blockIdx.z == 1) ? wk
                   : (blockIdx.z == 2) ? wv : wo;
    __half* Wt = wt + (size_t)blockIdx.z * DM * DM;
    __shared__ float tbuf[32][33];
    const int tx = threadIdx.x, ty = threadIdx.y;     // 32 x 8
    const int bx = blockIdx.x * 32, by = blockIdx.y * 32;
    #pragma unroll
    for (int j = 0; j < 32; j += 8)
        tbuf[ty + j][tx] = W[(size_t)(by + ty + j) * DM + bx + tx];
    __syncthreads();
    #pragma unroll
    for (int j = 0; j < 32; j += 8)
        Wt[(size_t)(bx + ty + j) * DM + by + tx] = __float2half_rn(tbuf[tx][ty + j]);
}

// ---------------------------------------------------------------------------
// Flash attention, fp16 HMMA. 256 threads (8 warps); warp w owns q rows
// [w*16, w*16+16) of a 128-row q-tile. KV tiles of 64, double-buffered cp.async.
// Q fragments cached in registers; K/V/P fragments via ldmatrix.x4.
// smem halfs: K[2][64][72], V[2][64][72] (V rows are d!), PQ[128][72]
// ---------------------------------------------------------------------------
#define FFP 72
#define FK_OFF  0
#define FV_OFF  (2*64*FFP)
#define FPQ_OFF (4*64*FFP)
#define FLASH_SMEM ((4*64*FFP + 128*FFP)*2)   // 55296 bytes

__global__ __launch_bounds__(256) void flash_kernel(__half* __restrict__ out)
{
    extern __shared__ __half sm[];
    const uint32_t sbase = smem_u32(sm);

    const int tid = threadIdx.x;
    const int lane = tid & 31, w = tid >> 5;
    const int g = lane >> 2, t = lane & 3;
    const int bh = blockIdx.y;
    const int q0 = blockIdx.x * 128;
    const int wq0 = w * 16;

    const int lr = lane & 15;
    const int lc = (lane >> 4) << 3;
    const int br = (lane & 7) + ((lane >> 4) << 3);
    const int bc = ((lane >> 3) & 1) << 3;

    const __half* Qg  = g_qh + (size_t)bh * SEQ * DH;
    const __half* Kg  = g_kh + (size_t)bh * SEQ * DH;
    const __half* Vtg = g_vt + (size_t)bh * DH * SEQ;

    auto issueKV = [&](int tt, int buf) {
        const int k0 = tt * 64;
        const uint32_t kb = sbase + (uint32_t)(FK_OFF + buf * 64 * FFP) * 2;
        #pragma unroll
        for (int i = tid; i < 512; i += 256) {
            const int r = i >> 3, c8 = (i & 7) * 8;
            cp16(kb + (uint32_t)(r * FFP + c8) * 2, Kg + (size_t)(k0 + r) * DH + c8);
        }
        const uint32_t vb = sbase + (uint32_t)(FV_OFF + buf * 64 * FFP) * 2;
        #pragma unroll
        for (int i = tid; i < 512; i += 256) {
            const int r = i >> 3, c8 = (i & 7) * 8;   // r = d, c8 along s
            cp16(vb + (uint32_t)(r * FFP + c8) * 2, Vtg + (size_t)r * SEQ + k0 + c8);
        }
        cp_commit();
    };

    // Prologue: Q tile (128x64) into PQ region; first two KV tiles
    #pragma unroll
    for (int i = tid; i < 1024; i += 256) {
        const int r = i >> 3, c8 = (i & 7) * 8;
        cp16(sbase + (uint32_t)(FPQ_OFF + r * FFP + c8) * 2, Qg + (size_t)(q0 + r) * DH + c8);
    }
    cp_commit();
    issueKV(0, 0);
    issueKV(1, 1);

    asm volatile("cp.async.wait_group 2;" ::: "memory");
    __syncthreads();

    // Q fragments to registers (own 16 rows)
    uint32_t qf[4][4];
    #pragma unroll
    for (int kk = 0; kk < 4; kk++)
        ldsm4(qf[kk][0], qf[kk][1], qf[kk][2], qf[kk][3],
              sbase + (uint32_t)(FPQ_OFF + (wq0 + lr) * FFP + kk * 16 + lc) * 2);

    float oacc[8][4];
    #pragma unroll
    for (int nf = 0; nf < 8; nf++)
        #pragma unroll
        for (int c = 0; c < 4; c++) oacc[nf][c] = 0.f;
    float m0r = -3.0e38f, m1r = -3.0e38f, l0 = 0.f, l1 = 0.f;
    const float sc = 0.125f;

    #pragma unroll 1
    for (int tt = 0; tt < 32; tt++) {
        const int buf = tt & 1;
        if (tt < 31) asm volatile("cp.async.wait_group 1;" ::: "memory");
        else         asm volatile("cp.async.wait_group 0;" ::: "memory");
        __syncthreads();

        const uint32_t kb = sbase + (uint32_t)(FK_OFF + buf * 64 * FFP) * 2;
        const uint32_t vb = sbase + (uint32_t)(FV_OFF + buf * 64 * FFP) * 2;

        // S = Q K^T (16 x 64 per warp)
        float sacc[8][4];
        #pragma unroll
        for (int nf = 0; nf < 8; nf++)
            #pragma unroll
            for (int c = 0; c < 4; c++) sacc[nf][c] = 0.f;

        #pragma unroll
        for (int kk = 0; kk < 4; kk++) {
            #pragma unroll
            for (int np = 0; np < 4; np++) {
                uint32_t b0, b1, b2, b3;
                ldsm4(b0, b1, b2, b3,
                      kb + (uint32_t)((np * 16 + br) * FFP + kk * 16 + bc) * 2);
                mma16(sacc[2 * np],     qf[kk], b0, b1);
                mma16(sacc[2 * np + 1], qf[kk], b2, b3);
            }
        }

        // Online softmax (rows wq0+g, wq0+g+8)
        float mx0 = -3.0e38f, mx1 = -3.0e38f;
        #pragma unroll
        for (int nf = 0; nf < 8; nf++) {
            sacc[nf][0] *= sc; sacc[nf][1] *= sc;
            sacc[nf][2] *= sc; sacc[nf][3] *= sc;
            mx0 = fmaxf(mx0, fmaxf(sacc[nf][0], sacc[nf][1]));
            mx1 = fmaxf(mx1, fmaxf(sacc[nf][2], sacc[nf][3]));
        }
        mx0 = fmaxf(mx0, __shfl_xor_sync(0xffffffffu, mx0, 1));
        mx0 = fmaxf(mx0, __shfl_xor_sync(0xffffffffu, mx0, 2));
        mx1 = fmaxf(mx1, __shfl_xor_sync(0xffffffffu, mx1, 1));
        mx1 = fmaxf(mx1, __shfl_xor_sync(0xffffffffu, mx1, 2));

        const float mn0 = fmaxf(m0r, mx0), mn1 = fmaxf(m1r, mx1);
        const float al0 = __expf(m0r - mn0), al1 = __expf(m1r - mn1);
        float s0 = 0.f, s1 = 0.f;
        #pragma unroll
        for (int nf = 0; nf < 8; nf++) {
            float p;
            p = __expf(sacc[nf][0] - mn0); sacc[nf][0] = p; s0 += p;
            p = __expf(sacc[nf][1] - mn0); sacc[nf][1] = p; s0 += p;
            p = __expf(sacc[nf][2] - mn1); sacc[nf][2] = p; s1 += p;
            p = __expf(sacc[nf][3] - mn1); sacc[nf][3] = p; s1 += p;
        }
        s0 += __shfl_xor_sync(0xffffffffu, s0, 1);
        s0 += __shfl_xor_sync(0xffffffffu, s0, 2);
        s1 += __shfl_xor_sync(0xffffffffu, s1, 1);
        s1 += __shfl_xor_sync(0xffffffffu, s1, 2);
        l0 = l0 * al0 + s0; m0r = mn0;
        l1 = l1 * al1 + s1; m1r = mn1;

        // Rescale O; stage P (own rows in PQ region)
        #pragma unroll
        for (int nf = 0; nf < 8; nf++) {
            oacc[nf][0] *= al0; oacc[nf][1] *= al0;
            oacc[nf][2] *= al1; oacc[nf][3] *= al1;
            const int pc = nf * 8 + 2 * t;
            *(uint32_t*)(sm + FPQ_OFF + (wq0 + g) * FFP + pc)     = pack_h2(sacc[nf][0], sacc[nf][1]);
            *(uint32_t*)(sm + FPQ_OFF + (wq0 + g + 8) * FFP + pc) = pack_h2(sacc[nf][2], sacc[nf][3]);
        }
        __syncwarp();

        // O += P V  (V rows are d: B-frags identical pattern to K)
        #pragma unroll
        for (int kk = 0; kk < 4; kk++) {
            uint32_t pa[4];
            ldsm4(pa[0], pa[1], pa[2], pa[3],
                  sbase + (uint32_t)(FPQ_OFF + (wq0 + lr) * FFP + kk * 16 + lc) * 2);
            #pragma unroll
            for (int np = 0; np < 4; np++) {
                uint32_t b0, b1, b2, b3;
                ldsm4(b0, b1, b2, b3,
                      vb + (uint32_t)((np * 16 + br) * FFP + kk * 16 + bc) * 2);
                mma16(oacc[2 * np],     pa, b0, b1);
                mma16(oacc[2 * np + 1], pa, b2, b3);
            }
        }
        __syncthreads();          // everyone done with buf before refill
        if (tt + 2 < 32) issueKV(tt + 2, buf);
    }

    // Normalize + write half to [b*s, d_model]
    const int b = bh >> 4, h = bh & 15;
    const float inv0 = 1.f / l0, inv1 = 1.f / l1;
    const int qrow = q0 + wq0 + g;
    #pragma unroll
    for (int nf = 0; nf < 8; nf++) {
        const int col = h * DH + nf * 8 + 2 * t;
        *(uint32_t*)(out + (size_t)(b * SEQ + qrow) * DM + col) =
            pack_h2(oacc[nf][0] * inv0, oacc[nf][1] * inv0);
        *(uint32_t*)(out + (size_t)(b * SEQ + qrow + 8) * DM + col) =
            pack_h2(oacc[nf][2] * inv1, oacc[nf][3] * inv1);
    }
}

// ---------------------------------------------------------------------------
extern "C" void kernel_launch(void* const* d_in, const int* in_sizes, int n_in,
                              void* d_out, int out_size)
{
    const float* v  = (const float*)d_in[0];
    const float* k  = (const float*)d_in[1];
    const float* q  = (const float*)d_in[2];
    const float* wq = (const float*)d_in[3];
    const float* bq = (const float*)d_in[4];
    const float* wk = (const float*)d_in[5];
    const float* bk = (const float*)d_in[6];
    const float* wv = (const float*)d_in[7];
    const float* bv = (const float*)d_in[8];
    const float* wo = (const float*)d_in[9];
    const float* bo = (const float*)d_in[10];
    float* out = (float*)d_out;

    __half *qh, *kh, *vt, *ao, *qc, *kc, *vc, *wt;
    cudaGetSymbolAddress((void**)&qh, g_qh);
    cudaGetSymbolAddress((void**)&kh, g_kh);
    cudaGetSymbolAddress((void**)&vt, g_vt);
    cudaGetSymbolAddress((void**)&ao, g_ao);
    cudaGetSymbolAddress((void**)&qc, g_qc);
    cudaGetSymbolAddress((void**)&kc, g_kc);
    cudaGetSymbolAddress((void**)&vc, g_vc);
    cudaGetSymbolAddress((void**)&wt, g_wt);

    cudaFuncSetAttribute(flash_kernel, cudaFuncAttributeMaxDynamicSharedMemorySize, FLASH_SMEM);

    // [0] convert q,k,v to half
    dim3 cgrid((MROWS * DM / 4) / 256, 3);
    cvt3_kernel<<<cgrid, 256>>>((const float4*)q, (const float4*)k, (const float4*)v,
                                (uint2*)qc, (uint2*)kc, (uint2*)vc);

    // [1] transpose+convert all 4 weights
    dim3 tgrid(DM / 32, DM / 32, 4);
    dim3 tblk(32, 8);
    transpose4_kernel<<<tgrid, tblk>>>(wq, wk, wv, wo, wt);

    // [2][3][4] projections
    dim3 gproj(DM / 128, MROWS / 128);   // (8, 64)
    tc_gemm<1, __half><<<gproj, 256, TCG_SMEM>>>(qc, wt + 0 * (size_t)DM * DM, bq, qh);
    tc_gemm<1, __half><<<gproj, 256, TCG_SMEM>>>(kc, wt + 1 * (size_t)DM * DM, bk, kh);
    tc_gemm<2, __half><<<gproj, 256, TCG_SMEM>>>(vc, wt + 2 * (size_t)DM * DM, bv, vt);

    // [5] flash attention  (launch index 5 -> profiled by ncu -s 5 -c 1)
    dim3 gattn(SEQ / 128, BATCH * NH);   // (16, 64)
    flash_kernel<<<gattn, 256, FLASH_SMEM>>>(ao);

    // [6] output projection
    tc_gemm<0, float><<<gproj, 256, TCG_SMEM>>>(ao, wt + 3 * (size_t)DM * DM, bo, out);
}